// round 14
// baseline (speedup 1.0000x reference)
#include <cuda_runtime.h>
#include <cuda_fp16.h>
#include <cstdint>

// HawkesKT single-kernel scheme with fused tile prep + cross-CTA flags:
// grid = (8 j-tiles x 64 batches); CTA (jt,b) preps i-tile jt of batch b into
// gmem (f16, PITCH layout), releases a flag, then consumes tiles jt..0
// (descending) via cp.async double-buffer, spin-acquiring producer flags.
// Spin has a bounded timeout -> idempotent self-gather fallback (deadlock-proof).
// Warp grid 4(Mj) x 4(Ni), warp tile 32x32; fused decay epilogue.
// B=64, L=1024, E=128.

#define NB   64
#define SEQL 1024
#define EMB  128
#define NSK  1000
#define NTHR 512

#define PITCH 272                  // bytes per tile row (136 f16), conflict-free ldmatrix
#define TILEB 34816                // 128 rows x 272
#define TILE2B 69632               // alpha + beta tile pair (= 4352 x 16B)

// smem offsets (bytes)
#define SJA 0
#define SJB 34816
#define BUF0 69632
#define BUF1 139264
#define TSF 208896                 // 1024 float times
#define RED 212992                 // 4 x 128 float
#define SMEM_BYTES 215040

// precomputed i-tiles + readiness flags
__device__ __align__(16) char gTileI[NB][8][TILE2B];
__device__ int gReady[NB][8];

__device__ __forceinline__ uint32_t smem_u32(const void* p) {
    uint32_t a;
    asm("{ .reg .u64 t; cvta.to.shared.u64 t, %1; cvt.u32.u64 %0, t; }" : "=r"(a) : "l"(p));
    return a;
}
__device__ __forceinline__ uint32_t pkh(float lo, float hi) {
    uint32_t r;
    asm("cvt.rn.f16x2.f32 %0, %1, %2;" : "=r"(r) : "f"(hi), "f"(lo)); // first src -> upper
    return r;
}
__device__ __forceinline__ void ldm_x4(uint32_t* r, uint32_t a) {
    asm volatile("ldmatrix.sync.aligned.m8n8.x4.shared.b16 {%0,%1,%2,%3}, [%4];"
                 : "=r"(r[0]), "=r"(r[1]), "=r"(r[2]), "=r"(r[3]) : "r"(a));
}
__device__ __forceinline__ void mma16816(float* c, const uint32_t* a, const uint32_t* b) {
    asm volatile(
        "mma.sync.aligned.m16n8k16.row.col.f32.f16.f16.f32 "
        "{%0,%1,%2,%3}, {%4,%5,%6,%7}, {%8,%9}, {%0,%1,%2,%3};"
        : "+f"(c[0]), "+f"(c[1]), "+f"(c[2]), "+f"(c[3])
        : "r"(a[0]), "r"(a[1]), "r"(a[2]), "r"(a[3]), "r"(b[0]), "r"(b[1]));
}
__device__ __forceinline__ float lg2f(float x) {
    float r; asm("lg2.approx.f32 %0, %1;" : "=f"(r) : "f"(x)); return r;
}
__device__ __forceinline__ float ex2f(float x) {
    float r; asm("ex2.approx.f32 %0, %1;" : "=f"(r) : "f"(x)); return r;
}
__device__ __forceinline__ void cpa16(uint32_t dst, const void* src) {
    asm volatile("cp.async.cg.shared.global [%0], [%1], 16;" :: "r"(dst), "l"(src) : "memory");
}
__device__ __forceinline__ void cpa_commit() {
    asm volatile("cp.async.commit_group;" ::: "memory");
}
__device__ __forceinline__ void cpa_wait1() {
    asm volatile("cp.async.wait_group 1;" ::: "memory");
}
__device__ __forceinline__ void st_release(int* p, int v) {
    asm volatile("st.global.release.gpu.b32 [%0], %1;" :: "l"(p), "r"(v) : "memory");
}
__device__ __forceinline__ int ld_acquire(const int* p) {
    int v;
    asm volatile("ld.global.acquire.gpu.b32 %0, [%1];" : "=r"(v) : "l"(p) : "memory");
    return v;
}

// Gather one table row-half (64 fp32 -> 64 f16) into a PITCH-row tile.
__device__ __forceinline__ void gather_half(const float* __restrict__ src,
                                            char* __restrict__ dstTile, int r, int h) {
    const float4* s4 = (const float4*)src + h * 16;
    char* dst = dstTile + r * PITCH + h * 128;
#pragma unroll
    for (int q = 0; q < 8; ++q) {
        float4 v0 = s4[q * 2];
        float4 v1 = s4[q * 2 + 1];
        uint4 w;
        w.x = pkh(v0.x, v0.y);
        w.y = pkh(v0.z, v0.w);
        w.z = pkh(v1.x, v1.y);
        w.w = pkh(v1.z, v1.w);
        *(uint4*)(dst + q * 16) = w;
    }
}

// Prep this thread's unit (1 of 512) of tile tt for batch b into gmem. Idempotent.
__device__ __forceinline__ void prep_unit(int b, int tt, const int* __restrict__ inp,
                                          const float* __restrict__ aI,
                                          const float* __restrict__ bI, int tid) {
    const int r = tid >> 2, h = (tid >> 1) & 1, tab = tid & 1;
    const int ig  = tt * 128 + r;
    const int sk  = inp[ig];
    const int lab = inp[2 * SEQL + ig];
    const int inter = sk + ((lab < 2) ? lab : 0) * NSK;
    gather_half((tab ? bI : aI) + (size_t)inter * EMB,
                gTileI[b][tt] + (tab ? TILEB : 0), r, h);
}

// async-copy one tile pair (69632 B) with 512 threads: 4352 16B chunks
__device__ __forceinline__ void copy_tilepair(uint32_t dstBase, const char* src, int tid) {
#pragma unroll
    for (int q = 0; q < 8; ++q) {
        const int idx = q * NTHR + tid;
        cpa16(dstBase + (uint32_t)idx * 16, src + (size_t)idx * 16);
    }
    const int idx8 = 8 * NTHR + tid;
    if (idx8 < TILE2B / 16) cpa16(dstBase + (uint32_t)idx8 * 16, src + (size_t)idx8 * 16);
}

__global__ void __launch_bounds__(NTHR, 1)
hawkes_fused1(const int*   __restrict__ input,
              const float* __restrict__ problem_base,
              const float* __restrict__ skill_base,
              const float* __restrict__ alpha_inter,
              const float* __restrict__ alpha_skill,
              const float* __restrict__ beta_inter,
              const float* __restrict__ beta_skill,
              float*       __restrict__ out)
{
    extern __shared__ char smem[];
    float* tsf = (float*)(smem + TSF);
    float* red = (float*)(smem + RED);
    const uint32_t sbase = smem_u32(smem);

    const int tid  = threadIdx.x;
    const int wid  = tid >> 5;
    const int lane = tid & 31;
    const int jt   = (int)gridDim.x - 1 - (int)blockIdx.x;   // heavy tiles first, batch-major bids
    const int b    = blockIdx.y;
    const int* __restrict__ inp = input + b * 4 * SEQL;
    const char* __restrict__ gI = gTileI[b][0];

    const int Mw = (wid & 3) * 32;    // warp j-base
    const int Nw = (wid >> 2) * 32;   // warp i-base
    const int g  = lane >> 2;
    const int t  = lane & 3;

    // ---- prep OWN tile jt into gmem, then release its flag ----
    prep_unit(b, jt, inp, alpha_inter, beta_inter, tid);
    __threadfence();
    __syncthreads();
    if (tid == 0) st_release(&gReady[b][jt], 1);

    // ---- prologue: async-copy own tile jt into buf[jt&1] ----
    copy_tilepair(sbase + ((jt & 1) ? BUF1 : BUF0), gI + (size_t)jt * TILE2B, tid);
    cpa_commit();

    // ---- times (as float) ----
    for (int i = tid; i < SEQL; i += NTHR) tsf[i] = (float)inp[3 * SEQL + i];

    // ---- j-side gather once: 512 units = 128 rows x 2 halves x 2 tables ----
    {
        const int gr = tid >> 2, gh = (tid >> 1) & 1, gtab = tid & 1;
        const int sk = inp[jt * 128 + gr];
        if (gtab == 0) gather_half(alpha_skill + (size_t)sk * EMB, smem + SJA, gr, gh);
        else           gather_half(beta_skill  + (size_t)sk * EMB, smem + SJB, gr, gh);
    }

    const uint32_t aRow = sbase + ((uint32_t)(Mw + (lane & 15)) * PITCH) + ((lane >> 4) & 1) * 16;
    const uint32_t bRowRel = ((uint32_t)(Nw + (lane & 7) + ((lane >> 4) & 1) * 8) * PITCH)
                             + ((lane >> 3) & 1) * 16;

    float ca[2][4][4], cb[2][4][4];
    float csum[4] = {0.f, 0.f, 0.f, 0.f};

    const int jtb = jt * 128;
    __syncthreads();   // tsf + SJ visible
    float tjf[4];
    int   jr[4];
#pragma unroll
    for (int q = 0; q < 4; ++q) {
        jr[q]  = Mw + (q >> 1) * 16 + (q & 1) * 8 + g;
        tjf[q] = tsf[jtb + jr[q]];
    }

    const float C1 = 0.6213349345596119f;  // 1/ln(5)

    for (int it = jt; it >= 0; --it) {
        // ---- acquire flag for tile it-1 (timeout -> idempotent self-prep), then
        //      issue its async copy into the other buffer ----
        if (it > 0) {
            const int tt = it - 1;
            int v = 0;
#pragma unroll 1
            for (int p = 0; p < 3000; ++p) {
                v = ld_acquire(&gReady[b][tt]);
                if (v) break;
            }
            if (!v) {   // fallback: regenerate own unit (same bytes; race-benign)
                prep_unit(b, tt, inp, alpha_inter, beta_inter, tid);
                __threadfence();
            }
            __syncthreads();   // all units of tile tt are in L2 (producer or self)
            copy_tilepair(sbase + ((tt & 1) ? BUF1 : BUF0),
                          gI + (size_t)tt * TILE2B, tid);
        }
        cpa_commit();            // empty group at it==0 keeps wait count aligned
        cpa_wait1();             // copy of tile it complete (this thread)
        __syncthreads();         // visible to all warps; prior buf reads retired

        const uint32_t bufc = (it & 1) ? BUF1 : BUF0;
        const uint32_t bRowA = sbase + bufc + bRowRel;
        const uint32_t bRowB = sbase + bufc + TILEB + bRowRel;

        // ---- zero accum + mainloop ----
#pragma unroll
        for (int mt = 0; mt < 2; ++mt)
#pragma unroll
            for (int nt = 0; nt < 4; ++nt)
#pragma unroll
                for (int e = 0; e < 4; ++e) { ca[mt][nt][e] = 0.f; cb[mt][nt][e] = 0.f; }

#pragma unroll
        for (int ks = 0; ks < 8; ++ks) {
            uint32_t Aa[2][4], Ab[2][4];
#pragma unroll
            for (int mt = 0; mt < 2; ++mt) {
                uint32_t ao = aRow + (uint32_t)mt * 16 * PITCH + (uint32_t)ks * 32;
                ldm_x4(Aa[mt], SJA + ao);
                ldm_x4(Ab[mt], SJB + ao);
            }
#pragma unroll
            for (int np = 0; np < 2; ++np) {
                uint32_t Ba[4], Bb[4];
                uint32_t bo = (uint32_t)np * 16 * PITCH + (uint32_t)ks * 32;
                ldm_x4(Ba, bRowA + bo);   // [n][k] row-major == B col-major for mma
                ldm_x4(Bb, bRowB + bo);
#pragma unroll
                for (int mt = 0; mt < 2; ++mt) {
                    mma16816(ca[mt][np * 2 + 0], Aa[mt], Ba + 0);
                    mma16816(ca[mt][np * 2 + 1], Aa[mt], Ba + 2);
                    mma16816(cb[mt][np * 2 + 0], Ab[mt], Bb + 0);
                    mma16816(cb[mt][np * 2 + 1], Ab[mt], Bb + 2);
                }
            }
        }
        __syncthreads();   // all B reads retired; next iter may overwrite buf^1

        // ---- epilogue (registers + tsf only) ----
        const int itb = it * 128;
        float tif[8];
#pragma unroll
        for (int nt = 0; nt < 4; ++nt) {
            tif[nt * 2 + 0] = tsf[itb + Nw + nt * 8 + 2 * t + 0];
            tif[nt * 2 + 1] = tsf[itb + Nw + nt * 8 + 2 * t + 1];
        }
        const bool diag = (it == jt);
#pragma unroll
        for (int mt = 0; mt < 2; ++mt)
#pragma unroll
            for (int nt = 0; nt < 4; ++nt)
#pragma unroll
                for (int e = 0; e < 4; ++e) {
                    const int q  = mt * 2 + (e >> 1);
                    const int ic = nt * 2 + (e & 1);
                    float d   = tif[ic] - tjf[q];
                    float l2  = lg2f(fabsf(d) + 1e-10f);
                    float bcs = fminf(fmaxf(cb[mt][nt][e] * C1 + C1, 0.0f), 10.0f * C1);
                    float dec = ex2f(-bcs * l2);
                    float contrib = ca[mt][nt][e] * dec;
                    if (diag) {
                        if ((Nw + nt * 8 + 2 * t + (e & 1)) < jr[q]) csum[q] += contrib;
                    } else {
                        csum[q] += contrib;
                    }
                }
    }

    // ---- reduce csum across quad lanes, then across the 4 N-warps via smem ----
#pragma unroll
    for (int q = 0; q < 4; ++q) {
        csum[q] += __shfl_xor_sync(0xFFFFFFFFu, csum[q], 1);
        csum[q] += __shfl_xor_sync(0xFFFFFFFFu, csum[q], 2);
    }
    const int wn = wid >> 2;
    if (t == 0) {
#pragma unroll
        for (int q = 0; q < 4; ++q)
            red[wn * 128 + jr[q]] = csum[q];
    }
    __syncthreads();

    if (tid < 128) {
        const int j = jtb + tid;
        float s = (red[tid] + red[128 + tid]) + (red[256 + tid] + red[384 + tid]);
        const int sk = inp[j];
        const int pr = inp[SEQL + j];
        float x = problem_base[pr] + skill_base[sk] + s;
        out[b * SEQL + j] = 1.0f / (1.0f + ex2f(-1.4426950408889634f * x));
    }
}

extern "C" void kernel_launch(void* const* d_in, const int* in_sizes, int n_in,
                              void* d_out, int out_size) {
    const int*   input        = (const int*)  d_in[0];
    const float* problem_base = (const float*)d_in[1];
    const float* skill_base   = (const float*)d_in[2];
    const float* alpha_inter  = (const float*)d_in[3];
    const float* alpha_skill  = (const float*)d_in[4];
    const float* beta_inter   = (const float*)d_in[5];
    const float* beta_skill   = (const float*)d_in[6];
    float* outp = (float*)d_out;

    cudaFuncSetAttribute(hawkes_fused1,
                         cudaFuncAttributeMaxDynamicSharedMemorySize, SMEM_BYTES);

    dim3 grid(SEQL / 128, NB);
    hawkes_fused1<<<grid, NTHR, SMEM_BYTES>>>(input, problem_base, skill_base,
                                              alpha_inter, alpha_skill,
                                              beta_inter, beta_skill, outp);
}

// round 15
// speedup vs baseline: 1.1324x; 1.1324x over previous
#include <cuda_runtime.h>
#include <cuda_fp16.h>
#include <cstdint>

// HawkesKT two-kernel scheme (R13 base + epilogue/mainloop overlap + wide prep):
//  1) prep kernel: gather+convert every i-side tile once into __device__ f16
//     PITCH-layout array (35.6 MB). grid (16,64): one row-half-table unit/thread.
//  2) main kernel: 16 warps (4/SMSP), warp grid 4(Mj) x 4(Ni), warp tile 32x32;
//     i-tiles via cp.async double-buffer. Loop order [wait0; sync; mainloop;
//     epilogue; sync; copy] puts mainloop+epilogue in ONE barrier window so
//     MUFU epilogue (warp X) overlaps LDSM/HMMA mainloop (warp Y).
// B=64, L=1024, E=128.

#define NB   64
#define SEQL 1024
#define EMB  128
#define NSK  1000
#define NTHR 512

#define PITCH 272                  // bytes per tile row (136 f16), conflict-free ldmatrix
#define TILEB 34816                // 128 rows x 272
#define TILE2B 69632               // alpha + beta tile pair (= 4352 x 16B)

// smem offsets (bytes)
#define SJA 0
#define SJB 34816
#define BUF0 69632
#define BUF1 139264
#define TSF 208896                 // 1024 float times
#define RED 212992                 // 4 x 128 float
#define SMEM_BYTES 215040

// precomputed i-tiles: [batch][tile][alpha tile | beta tile]
__device__ __align__(16) char gTileI[NB][8][TILE2B];

__device__ __forceinline__ uint32_t smem_u32(const void* p) {
    uint32_t a;
    asm("{ .reg .u64 t; cvta.to.shared.u64 t, %1; cvt.u32.u64 %0, t; }" : "=r"(a) : "l"(p));
    return a;
}
__device__ __forceinline__ uint32_t pkh(float lo, float hi) {
    uint32_t r;
    asm("cvt.rn.f16x2.f32 %0, %1, %2;" : "=r"(r) : "f"(hi), "f"(lo)); // first src -> upper
    return r;
}
__device__ __forceinline__ void ldm_x4(uint32_t* r, uint32_t a) {
    asm volatile("ldmatrix.sync.aligned.m8n8.x4.shared.b16 {%0,%1,%2,%3}, [%4];"
                 : "=r"(r[0]), "=r"(r[1]), "=r"(r[2]), "=r"(r[3]) : "r"(a));
}
__device__ __forceinline__ void mma16816(float* c, const uint32_t* a, const uint32_t* b) {
    asm volatile(
        "mma.sync.aligned.m16n8k16.row.col.f32.f16.f16.f32 "
        "{%0,%1,%2,%3}, {%4,%5,%6,%7}, {%8,%9}, {%0,%1,%2,%3};"
        : "+f"(c[0]), "+f"(c[1]), "+f"(c[2]), "+f"(c[3])
        : "r"(a[0]), "r"(a[1]), "r"(a[2]), "r"(a[3]), "r"(b[0]), "r"(b[1]));
}
__device__ __forceinline__ float lg2f(float x) {
    float r; asm("lg2.approx.f32 %0, %1;" : "=f"(r) : "f"(x)); return r;
}
__device__ __forceinline__ float ex2f(float x) {
    float r; asm("ex2.approx.f32 %0, %1;" : "=f"(r) : "f"(x)); return r;
}
__device__ __forceinline__ void cpa16(uint32_t dst, const void* src) {
    asm volatile("cp.async.cg.shared.global [%0], [%1], 16;" :: "r"(dst), "l"(src) : "memory");
}
__device__ __forceinline__ void cpa_commit() {
    asm volatile("cp.async.commit_group;" ::: "memory");
}
__device__ __forceinline__ void cpa_wait0() {
    asm volatile("cp.async.wait_group 0;" ::: "memory");
}

// Gather one table row-half (64 fp32 -> 64 f16) into a PITCH-row tile.
__device__ __forceinline__ void gather_half(const float* __restrict__ src,
                                            char* __restrict__ dstTile, int r, int h) {
    const float4* s4 = (const float4*)src + h * 16;
    char* dst = dstTile + r * PITCH + h * 128;
#pragma unroll
    for (int q = 0; q < 8; ++q) {
        float4 v0 = s4[q * 2];
        float4 v1 = s4[q * 2 + 1];
        uint4 w;
        w.x = pkh(v0.x, v0.y);
        w.y = pkh(v0.z, v0.w);
        w.z = pkh(v1.x, v1.y);
        w.w = pkh(v1.z, v1.w);
        *(uint4*)(dst + q * 16) = w;
    }
}

// ---------------- prepass: materialize i-tiles (1 unit per thread) ----------------
__global__ void __launch_bounds__(256, 4)
hawkes_prep(const int*   __restrict__ input,
            const float* __restrict__ alpha_inter,
            const float* __restrict__ beta_inter)
{
    const int tile = blockIdx.x >> 1;     // 0..7
    const int rhalf = blockIdx.x & 1;     // row half 0/1
    const int b    = blockIdx.y;          // batch
    const int tid  = threadIdx.x;
    const int* __restrict__ inp = input + b * 4 * SEQL;
    char* dstPair = gTileI[b][tile];

    const int r   = rhalf * 64 + (tid >> 2);
    const int h   = (tid >> 1) & 1;
    const int tab = tid & 1;
    const int ig  = tile * 128 + r;
    const int sk  = inp[ig];
    const int lab = inp[2 * SEQL + ig];
    const int inter = sk + ((lab < 2) ? lab : 0) * NSK;
    if (tab == 0)
        gather_half(alpha_inter + (size_t)inter * EMB, dstPair, r, h);
    else
        gather_half(beta_inter + (size_t)inter * EMB, dstPair + TILEB, r, h);
}

// async-copy one tile pair (69632 B) with 512 threads: 4352 16B chunks
__device__ __forceinline__ void copy_tilepair(uint32_t dstBase, const char* src, int tid) {
#pragma unroll
    for (int q = 0; q < 8; ++q) {
        const int idx = q * NTHR + tid;
        cpa16(dstBase + (uint32_t)idx * 16, src + (size_t)idx * 16);
    }
    const int idx8 = 8 * NTHR + tid;
    if (idx8 < TILE2B / 16) cpa16(dstBase + (uint32_t)idx8 * 16, src + (size_t)idx8 * 16);
}

// ---------------- main kernel ----------------
__global__ void __launch_bounds__(NTHR, 1)
hawkes_main(const int*   __restrict__ input,
            const float* __restrict__ problem_base,
            const float* __restrict__ skill_base,
            const float* __restrict__ alpha_skill,
            const float* __restrict__ beta_skill,
            float*       __restrict__ out)
{
    extern __shared__ char smem[];
    float* tsf = (float*)(smem + TSF);
    float* red = (float*)(smem + RED);
    const uint32_t sbase = smem_u32(smem);

    const int tid  = threadIdx.x;
    const int wid  = tid >> 5;
    const int lane = tid & 31;
    const int jt   = (int)gridDim.x - 1 - (int)blockIdx.x;   // heavy tiles first
    const int b    = blockIdx.y;
    const int* __restrict__ inp = input + b * 4 * SEQL;
    const char* __restrict__ gI = gTileI[b][0];

    const int Mw = (wid & 3) * 32;    // warp j-base
    const int Nw = (wid >> 2) * 32;   // warp i-base
    const int g  = lane >> 2;
    const int t  = lane & 3;

    // ---- prologue: async-copy i-tile 0 into buf0 ----
    copy_tilepair(sbase + BUF0, gI, tid);
    cpa_commit();

    // ---- times (as float) ----
    for (int i = tid; i < SEQL; i += NTHR) tsf[i] = (float)inp[3 * SEQL + i];

    // ---- j-side gather once: 512 units = 128 rows x 2 halves x 2 tables ----
    {
        const int gr = tid >> 2, gh = (tid >> 1) & 1, gtab = tid & 1;
        const int sk = inp[jt * 128 + gr];
        if (gtab == 0) gather_half(alpha_skill + (size_t)sk * EMB, smem + SJA, gr, gh);
        else           gather_half(beta_skill  + (size_t)sk * EMB, smem + SJB, gr, gh);
    }

    const uint32_t aRow = sbase + ((uint32_t)(Mw + (lane & 15)) * PITCH) + ((lane >> 4) & 1) * 16;
    const uint32_t bRowRel = ((uint32_t)(Nw + (lane & 7) + ((lane >> 4) & 1) * 8) * PITCH)
                             + ((lane >> 3) & 1) * 16;

    float ca[2][4][4], cb[2][4][4];
    float csum[4] = {0.f, 0.f, 0.f, 0.f};

    const int jtb = jt * 128;
    __syncthreads();   // tsf + SJ visible
    float tjf[4];
    int   jr[4];
#pragma unroll
    for (int q = 0; q < 4; ++q) {
        jr[q]  = Mw + (q >> 1) * 16 + (q & 1) * 8 + g;
        tjf[q] = tsf[jtb + jr[q]];
    }

    const float C1 = 0.6213349345596119f;  // 1/ln(5)

    for (int it = 0; it <= jt; ++it) {
        cpa_wait0();             // copy of tile it complete (this thread's chunks)
        __syncthreads();         // smem writes visible CTA-wide; buf^1 reads (it-2) long retired

        const uint32_t bufc = (it & 1) ? BUF1 : BUF0;
        const uint32_t bRowA = sbase + bufc + bRowRel;
        const uint32_t bRowB = sbase + bufc + TILEB + bRowRel;

        // ---- zero accum + mainloop ----
#pragma unroll
        for (int mt = 0; mt < 2; ++mt)
#pragma unroll
            for (int nt = 0; nt < 4; ++nt)
#pragma unroll
                for (int e = 0; e < 4; ++e) { ca[mt][nt][e] = 0.f; cb[mt][nt][e] = 0.f; }

#pragma unroll
        for (int ks = 0; ks < 8; ++ks) {
            uint32_t Aa[2][4], Ab[2][4];
#pragma unroll
            for (int mt = 0; mt < 2; ++mt) {
                uint32_t ao = aRow + (uint32_t)mt * 16 * PITCH + (uint32_t)ks * 32;
                ldm_x4(Aa[mt], SJA + ao);
                ldm_x4(Ab[mt], SJB + ao);
            }
#pragma unroll
            for (int np = 0; np < 2; ++np) {
                uint32_t Ba[4], Bb[4];
                uint32_t bo = (uint32_t)np * 16 * PITCH + (uint32_t)ks * 32;
                ldm_x4(Ba, bRowA + bo);   // [n][k] row-major == B col-major for mma
                ldm_x4(Bb, bRowB + bo);
#pragma unroll
                for (int mt = 0; mt < 2; ++mt) {
                    mma16816(ca[mt][np * 2 + 0], Aa[mt], Ba + 0);
                    mma16816(ca[mt][np * 2 + 1], Aa[mt], Ba + 2);
                    mma16816(cb[mt][np * 2 + 0], Ab[mt], Bb + 0);
                    mma16816(cb[mt][np * 2 + 1], Ab[mt], Bb + 2);
                }
            }
        }

        // ---- epilogue in the SAME barrier window: overlaps other warps' mainloop ----
        const int itb = it * 128;
        float tif[8];
#pragma unroll
        for (int nt = 0; nt < 4; ++nt) {
            tif[nt * 2 + 0] = tsf[itb + Nw + nt * 8 + 2 * t + 0];
            tif[nt * 2 + 1] = tsf[itb + Nw + nt * 8 + 2 * t + 1];
        }
        const bool diag = (it == jt);
#pragma unroll
        for (int mt = 0; mt < 2; ++mt)
#pragma unroll
            for (int nt = 0; nt < 4; ++nt)
#pragma unroll
                for (int e = 0; e < 4; ++e) {
                    const int q  = mt * 2 + (e >> 1);
                    const int ic = nt * 2 + (e & 1);
                    float d   = tif[ic] - tjf[q];
                    float l2  = lg2f(fabsf(d) + 1e-10f);
                    float bcs = fminf(fmaxf(cb[mt][nt][e] * C1 + C1, 0.0f), 10.0f * C1);
                    float dec = ex2f(-bcs * l2);
                    float contrib = ca[mt][nt][e] * dec;
                    if (diag) {
                        if ((Nw + nt * 8 + 2 * t + (e & 1)) < jr[q]) csum[q] += contrib;
                    } else {
                        csum[q] += contrib;
                    }
                }

        __syncthreads();   // all warps done reading buf[it&1]; safe to refill buf^1
        if (it < jt) {
            copy_tilepair(sbase + (((it + 1) & 1) ? BUF1 : BUF0),
                          gI + (size_t)(it + 1) * TILE2B, tid);
            cpa_commit();
        }
    }

    // ---- reduce csum across quad lanes, then across the 4 N-warps via smem ----
#pragma unroll
    for (int q = 0; q < 4; ++q) {
        csum[q] += __shfl_xor_sync(0xFFFFFFFFu, csum[q], 1);
        csum[q] += __shfl_xor_sync(0xFFFFFFFFu, csum[q], 2);
    }
    const int wn = wid >> 2;
    if (t == 0) {
#pragma unroll
        for (int q = 0; q < 4; ++q)
            red[wn * 128 + jr[q]] = csum[q];
    }
    __syncthreads();

    if (tid < 128) {
        const int j = jtb + tid;
        float s = (red[tid] + red[128 + tid]) + (red[256 + tid] + red[384 + tid]);
        const int sk = inp[j];
        const int pr = inp[SEQL + j];
        float x = problem_base[pr] + skill_base[sk] + s;
        out[b * SEQL + j] = 1.0f / (1.0f + ex2f(-1.4426950408889634f * x));
    }
}

extern "C" void kernel_launch(void* const* d_in, const int* in_sizes, int n_in,
                              void* d_out, int out_size) {
    const int*   input        = (const int*)  d_in[0];
    const float* problem_base = (const float*)d_in[1];
    const float* skill_base   = (const float*)d_in[2];
    const float* alpha_inter  = (const float*)d_in[3];
    const float* alpha_skill  = (const float*)d_in[4];
    const float* beta_inter   = (const float*)d_in[5];
    const float* beta_skill   = (const float*)d_in[6];
    float* outp = (float*)d_out;

    cudaFuncSetAttribute(hawkes_main,
                         cudaFuncAttributeMaxDynamicSharedMemorySize, SMEM_BYTES);

    dim3 pgrid(16, NB);
    hawkes_prep<<<pgrid, 256>>>(input, alpha_inter, beta_inter);

    dim3 grid(SEQL / 128, NB);
    hawkes_main<<<grid, NTHR, SMEM_BYTES>>>(input, problem_base, skill_base,
                                            alpha_skill, beta_skill, outp);
}

// round 16
// speedup vs baseline: 1.1592x; 1.0237x over previous
#include <cuda_runtime.h>
#include <cuda_fp16.h>
#include <cstdint>

// HawkesKT two-kernel scheme (R13 loop order + R15 wide prep + diag-warp skip):
//  1) prep kernel: gather+convert every i-side tile once into __device__ f16
//     PITCH-layout array (35.6 MB). grid (16,64): one row-half-table unit/thread.
//  2) main kernel: 16 warps (4/SMSP), warp grid 4(Mj) x 4(Ni), warp tile 32x32;
//     i-tiles via cp.async double-buffer (copy issued a full tile ahead);
//     diag tile: warps with Nw >= Mw+32 are fully masked -> skip their work.
// B=64, L=1024, E=128.

#define NB   64
#define SEQL 1024
#define EMB  128
#define NSK  1000
#define NTHR 512

#define PITCH 272                  // bytes per tile row (136 f16), conflict-free ldmatrix
#define TILEB 34816                // 128 rows x 272
#define TILE2B 69632               // alpha + beta tile pair (= 4352 x 16B)

// smem offsets (bytes)
#define SJA 0
#define SJB 34816
#define BUF0 69632
#define BUF1 139264
#define TSF 208896                 // 1024 float times
#define RED 212992                 // 4 x 128 float
#define SMEM_BYTES 215040

// precomputed i-tiles: [batch][tile][alpha tile | beta tile]
__device__ __align__(16) char gTileI[NB][8][TILE2B];

__device__ __forceinline__ uint32_t smem_u32(const void* p) {
    uint32_t a;
    asm("{ .reg .u64 t; cvta.to.shared.u64 t, %1; cvt.u32.u64 %0, t; }" : "=r"(a) : "l"(p));
    return a;
}
__device__ __forceinline__ uint32_t pkh(float lo, float hi) {
    uint32_t r;
    asm("cvt.rn.f16x2.f32 %0, %1, %2;" : "=r"(r) : "f"(hi), "f"(lo)); // first src -> upper
    return r;
}
__device__ __forceinline__ void ldm_x4(uint32_t* r, uint32_t a) {
    asm volatile("ldmatrix.sync.aligned.m8n8.x4.shared.b16 {%0,%1,%2,%3}, [%4];"
                 : "=r"(r[0]), "=r"(r[1]), "=r"(r[2]), "=r"(r[3]) : "r"(a));
}
__device__ __forceinline__ void mma16816(float* c, const uint32_t* a, const uint32_t* b) {
    asm volatile(
        "mma.sync.aligned.m16n8k16.row.col.f32.f16.f16.f32 "
        "{%0,%1,%2,%3}, {%4,%5,%6,%7}, {%8,%9}, {%0,%1,%2,%3};"
        : "+f"(c[0]), "+f"(c[1]), "+f"(c[2]), "+f"(c[3])
        : "r"(a[0]), "r"(a[1]), "r"(a[2]), "r"(a[3]), "r"(b[0]), "r"(b[1]));
}
__device__ __forceinline__ float lg2f(float x) {
    float r; asm("lg2.approx.f32 %0, %1;" : "=f"(r) : "f"(x)); return r;
}
__device__ __forceinline__ float ex2f(float x) {
    float r; asm("ex2.approx.f32 %0, %1;" : "=f"(r) : "f"(x)); return r;
}
__device__ __forceinline__ void cpa16(uint32_t dst, const void* src) {
    asm volatile("cp.async.cg.shared.global [%0], [%1], 16;" :: "r"(dst), "l"(src) : "memory");
}
__device__ __forceinline__ void cpa_commit() {
    asm volatile("cp.async.commit_group;" ::: "memory");
}
__device__ __forceinline__ void cpa_wait1() {
    asm volatile("cp.async.wait_group 1;" ::: "memory");
}

// Gather one table row-half (64 fp32 -> 64 f16) into a PITCH-row tile.
__device__ __forceinline__ void gather_half(const float* __restrict__ src,
                                            char* __restrict__ dstTile, int r, int h) {
    const float4* s4 = (const float4*)src + h * 16;
    char* dst = dstTile + r * PITCH + h * 128;
#pragma unroll
    for (int q = 0; q < 8; ++q) {
        float4 v0 = s4[q * 2];
        float4 v1 = s4[q * 2 + 1];
        uint4 w;
        w.x = pkh(v0.x, v0.y);
        w.y = pkh(v0.z, v0.w);
        w.z = pkh(v1.x, v1.y);
        w.w = pkh(v1.z, v1.w);
        *(uint4*)(dst + q * 16) = w;
    }
}

// ---------------- prepass: materialize i-tiles (1 unit per thread) ----------------
__global__ void __launch_bounds__(256, 4)
hawkes_prep(const int*   __restrict__ input,
            const float* __restrict__ alpha_inter,
            const float* __restrict__ beta_inter)
{
    const int tile = blockIdx.x >> 1;     // 0..7
    const int rhalf = blockIdx.x & 1;     // row half 0/1
    const int b    = blockIdx.y;          // batch
    const int tid  = threadIdx.x;
    const int* __restrict__ inp = input + b * 4 * SEQL;
    char* dstPair = gTileI[b][tile];

    const int r   = rhalf * 64 + (tid >> 2);
    const int h   = (tid >> 1) & 1;
    const int tab = tid & 1;
    const int ig  = tile * 128 + r;
    const int sk  = inp[ig];
    const int lab = inp[2 * SEQL + ig];
    const int inter = sk + ((lab < 2) ? lab : 0) * NSK;
    if (tab == 0)
        gather_half(alpha_inter + (size_t)inter * EMB, dstPair, r, h);
    else
        gather_half(beta_inter + (size_t)inter * EMB, dstPair + TILEB, r, h);
}

// async-copy one tile pair (69632 B) with 512 threads: 4352 16B chunks
__device__ __forceinline__ void copy_tilepair(uint32_t dstBase, const char* src, int tid) {
#pragma unroll
    for (int q = 0; q < 8; ++q) {
        const int idx = q * NTHR + tid;
        cpa16(dstBase + (uint32_t)idx * 16, src + (size_t)idx * 16);
    }
    const int idx8 = 8 * NTHR + tid;
    if (idx8 < TILE2B / 16) cpa16(dstBase + (uint32_t)idx8 * 16, src + (size_t)idx8 * 16);
}

// ---------------- main kernel ----------------
__global__ void __launch_bounds__(NTHR, 1)
hawkes_main(const int*   __restrict__ input,
            const float* __restrict__ problem_base,
            const float* __restrict__ skill_base,
            const float* __restrict__ alpha_skill,
            const float* __restrict__ beta_skill,
            float*       __restrict__ out)
{
    extern __shared__ char smem[];
    float* tsf = (float*)(smem + TSF);
    float* red = (float*)(smem + RED);
    const uint32_t sbase = smem_u32(smem);

    const int tid  = threadIdx.x;
    const int wid  = tid >> 5;
    const int lane = tid & 31;
    const int jt   = (int)gridDim.x - 1 - (int)blockIdx.x;   // heavy tiles first
    const int b    = blockIdx.y;
    const int* __restrict__ inp = input + b * 4 * SEQL;
    const char* __restrict__ gI = gTileI[b][0];

    const int Mw = (wid & 3) * 32;    // warp j-base
    const int Nw = (wid >> 2) * 32;   // warp i-base
    const int g  = lane >> 2;
    const int t  = lane & 3;
    const bool diagSkip = (Nw >= Mw + 32);   // on diag tile, fully masked

    // ---- prologue: async-copy i-tile 0 into buf0 ----
    copy_tilepair(sbase + BUF0, gI, tid);
    cpa_commit();

    // ---- times (as float) ----
    for (int i = tid; i < SEQL; i += NTHR) tsf[i] = (float)inp[3 * SEQL + i];

    // ---- j-side gather once: 512 units = 128 rows x 2 halves x 2 tables ----
    {
        const int gr = tid >> 2, gh = (tid >> 1) & 1, gtab = tid & 1;
        const int sk = inp[jt * 128 + gr];
        if (gtab == 0) gather_half(alpha_skill + (size_t)sk * EMB, smem + SJA, gr, gh);
        else           gather_half(beta_skill  + (size_t)sk * EMB, smem + SJB, gr, gh);
    }

    const uint32_t aRow = sbase + ((uint32_t)(Mw + (lane & 15)) * PITCH) + ((lane >> 4) & 1) * 16;
    const uint32_t bRowRel = ((uint32_t)(Nw + (lane & 7) + ((lane >> 4) & 1) * 8) * PITCH)
                             + ((lane >> 3) & 1) * 16;

    float ca[2][4][4], cb[2][4][4];
    float csum[4] = {0.f, 0.f, 0.f, 0.f};

    const int jtb = jt * 128;
    __syncthreads();   // tsf + SJ visible
    float tjf[4];
    int   jr[4];
#pragma unroll
    for (int q = 0; q < 4; ++q) {
        jr[q]  = Mw + (q >> 1) * 16 + (q & 1) * 8 + g;
        tjf[q] = tsf[jtb + jr[q]];
    }

    const float C1 = 0.6213349345596119f;  // 1/ln(5)

    for (int it = 0; it <= jt; ++it) {
        // ---- issue async copy of tile it+1 into the other buffer ----
        if (it < jt)
            copy_tilepair(sbase + (((it + 1) & 1) ? BUF1 : BUF0),
                          gI + (size_t)(it + 1) * TILE2B, tid);
        cpa_commit();            // empty group when it == jt keeps wait count aligned
        cpa_wait1();             // current tile's group complete
        __syncthreads();         // visible to all warps; prior buf reads retired

        const bool diag = (it == jt);
        const bool skip = diag && diagSkip;

        const uint32_t bufc = (it & 1) ? BUF1 : BUF0;
        const uint32_t bRowA = sbase + bufc + bRowRel;
        const uint32_t bRowB = sbase + bufc + TILEB + bRowRel;

        if (!skip) {
            // ---- zero accum + mainloop ----
#pragma unroll
            for (int mt = 0; mt < 2; ++mt)
#pragma unroll
                for (int nt = 0; nt < 4; ++nt)
#pragma unroll
                    for (int e = 0; e < 4; ++e) { ca[mt][nt][e] = 0.f; cb[mt][nt][e] = 0.f; }

#pragma unroll
            for (int ks = 0; ks < 8; ++ks) {
                uint32_t Aa[2][4], Ab[2][4];
#pragma unroll
                for (int mt = 0; mt < 2; ++mt) {
                    uint32_t ao = aRow + (uint32_t)mt * 16 * PITCH + (uint32_t)ks * 32;
                    ldm_x4(Aa[mt], SJA + ao);
                    ldm_x4(Ab[mt], SJB + ao);
                }
#pragma unroll
                for (int np = 0; np < 2; ++np) {
                    uint32_t Ba[4], Bb[4];
                    uint32_t bo = (uint32_t)np * 16 * PITCH + (uint32_t)ks * 32;
                    ldm_x4(Ba, bRowA + bo);   // [n][k] row-major == B col-major for mma
                    ldm_x4(Bb, bRowB + bo);
#pragma unroll
                    for (int mt = 0; mt < 2; ++mt) {
                        mma16816(ca[mt][np * 2 + 0], Aa[mt], Ba + 0);
                        mma16816(ca[mt][np * 2 + 1], Aa[mt], Ba + 2);
                        mma16816(cb[mt][np * 2 + 0], Ab[mt], Bb + 0);
                        mma16816(cb[mt][np * 2 + 1], Ab[mt], Bb + 2);
                    }
                }
            }
        }
        __syncthreads();   // all B reads retired; next iter may overwrite buf^1

        if (!skip) {
            // ---- epilogue (registers + tsf only): overlaps next copy + wait ----
            const int itb = it * 128;
            float tif[8];
#pragma unroll
            for (int nt = 0; nt < 4; ++nt) {
                tif[nt * 2 + 0] = tsf[itb + Nw + nt * 8 + 2 * t + 0];
                tif[nt * 2 + 1] = tsf[itb + Nw + nt * 8 + 2 * t + 1];
            }
#pragma unroll
            for (int mt = 0; mt < 2; ++mt)
#pragma unroll
                for (int nt = 0; nt < 4; ++nt)
#pragma unroll
                    for (int e = 0; e < 4; ++e) {
                        const int q  = mt * 2 + (e >> 1);
                        const int ic = nt * 2 + (e & 1);
                        float d   = tif[ic] - tjf[q];
                        float l2  = lg2f(fabsf(d) + 1e-10f);
                        float bcs = fminf(fmaxf(cb[mt][nt][e] * C1 + C1, 0.0f), 10.0f * C1);
                        float dec = ex2f(-bcs * l2);
                        float contrib = ca[mt][nt][e] * dec;
                        if (diag) {
                            if ((Nw + nt * 8 + 2 * t + (e & 1)) < jr[q]) csum[q] += contrib;
                        } else {
                            csum[q] += contrib;
                        }
                    }
        }
    }

    // ---- reduce csum across quad lanes, then across the 4 N-warps via smem ----
#pragma unroll
    for (int q = 0; q < 4; ++q) {
        csum[q] += __shfl_xor_sync(0xFFFFFFFFu, csum[q], 1);
        csum[q] += __shfl_xor_sync(0xFFFFFFFFu, csum[q], 2);
    }
    const int wn = wid >> 2;
    if (t == 0) {
#pragma unroll
        for (int q = 0; q < 4; ++q)
            red[wn * 128 + jr[q]] = csum[q];
    }
    __syncthreads();

    if (tid < 128) {
        const int j = jtb + tid;
        float s = (red[tid] + red[128 + tid]) + (red[256 + tid] + red[384 + tid]);
        const int sk = inp[j];
        const int pr = inp[SEQL + j];
        float x = problem_base[pr] + skill_base[sk] + s;
        out[b * SEQL + j] = 1.0f / (1.0f + ex2f(-1.4426950408889634f * x));
    }
}

extern "C" void kernel_launch(void* const* d_in, const int* in_sizes, int n_in,
                              void* d_out, int out_size) {
    const int*   input        = (const int*)  d_in[0];
    const float* problem_base = (const float*)d_in[1];
    const float* skill_base   = (const float*)d_in[2];
    const float* alpha_inter  = (const float*)d_in[3];
    const float* alpha_skill  = (const float*)d_in[4];
    const float* beta_inter   = (const float*)d_in[5];
    const float* beta_skill   = (const float*)d_in[6];
    float* outp = (float*)d_out;

    cudaFuncSetAttribute(hawkes_main,
                         cudaFuncAttributeMaxDynamicSharedMemorySize, SMEM_BYTES);

    dim3 pgrid(16, NB);
    hawkes_prep<<<pgrid, 256>>>(input, alpha_inter, beta_inter);

    dim3 grid(SEQL / 128, NB);
    hawkes_main<<<grid, NTHR, SMEM_BYTES>>>(input, problem_base, skill_base,
                                            alpha_skill, beta_skill, outp);
}